// round 15
// baseline (speedup 1.0000x reference)
#include <cuda_runtime.h>
#include <cuda_fp16.h>
#include <cstdint>

#define N_NODES 50000
#define N_EDGES 800000
#define IN_CH   256
#define OUT_CH  64
#define HEADS   4
#define OUTF    (HEADS * OUT_CH)   // 256

#define SCAN_BLOCKS 49             // ceil(50000/1024)

// ---------------- device scratch (no allocs allowed) ----------------
__device__ __align__(16) __half g_xhh[(size_t)N_NODES * OUTF];  // projected features, fp16
__device__ __align__(16) __half g_wcatT[OUTF * IN_CH];          // weight^T fp16: [n=256][k=256]
__device__ __align__(16) float g_asrc[N_NODES * HEADS];         // [N, 4]
__device__ __align__(16) float g_adst[N_NODES * HEADS];         // [N, 4]
__device__ int g_cnt[N_NODES];                                  // per-row edge count (self-zeroing)
__device__ int g_off[N_NODES + 1];                              // CSR offsets
__device__ int g_cur[N_NODES];                                  // reorder cursors
__device__ int g_tile_agg[64];                                  // scan tile aggregates
__device__ int g_tile_pre[64];                                  // scan tile prefixes
__device__ int g_tile_flag[64];                                 // 0=empty,1=agg,2=prefix (self-zeroing)
__device__ int g_ecol[N_EDGES];                                 // CSR col per slot
__device__ __align__(16) float g_eexp[(size_t)N_EDGES * HEADS]; // CSR exp(logit) per slot

__device__ __forceinline__ int clamp_idx(int v) {
    return min(max(v, 0), N_NODES - 1);
}

__device__ __forceinline__ void mma_f16(float* c, const uint32_t* a, uint32_t b0, uint32_t b1) {
    asm("mma.sync.aligned.m16n8k16.row.col.f32.f16.f16.f32 "
        "{%0,%1,%2,%3}, {%4,%5,%6,%7}, {%8,%9}, {%0,%1,%2,%3};"
        : "+f"(c[0]), "+f"(c[1]), "+f"(c[2]), "+f"(c[3])
        : "r"(a[0]), "r"(a[1]), "r"(a[2]), "r"(a[3]), "r"(b0), "r"(b1));
}

__device__ __forceinline__ void ldmx4(uint32_t& r0, uint32_t& r1, uint32_t& r2, uint32_t& r3,
                                      uint32_t addr) {
    asm volatile("ldmatrix.sync.aligned.m8n8.x4.shared.b16 {%0,%1,%2,%3}, [%4];"
                 : "=r"(r0), "=r"(r1), "=r"(r2), "=r"(r3) : "r"(addr));
}

// ---------------- hist + weight transpose (merged; ordering vs gemm by launch order) ----
__global__ void k_hist(const int* __restrict__ ei, const float* __restrict__ w) {
    int i = blockIdx.x * blockDim.x + threadIdx.x;
    if (i < HEADS * IN_CH * OUT_CH) {
        int h = i >> 14;
        int f = (i >> 6) & 255;
        int c = i & 63;
        g_wcatT[(size_t)(h * OUT_CH + c) * IN_CH + f] = __float2half(w[i]);
    }
    if (i < N_EDGES) atomicAdd(&g_cnt[clamp_idx(ei[i])], 1);
}

// ---------------- single-kernel scan: 49 co-resident blocks; self-cleaning ----------------
__global__ void k_scanL() {
    __shared__ int wsum[32];
    __shared__ int sh_pre;
    const int b = blockIdx.x;
    const int t = threadIdx.x;
    const int i = b * 1024 + t;
    const int lane = t & 31, wid = t >> 5;

    int v = (i < N_NODES) ? g_cnt[i] : 0;
    if (i < N_NODES) g_cnt[i] = 0;                 // reset for next graph replay
    int inc = v;
    #pragma unroll
    for (int d = 1; d < 32; d <<= 1) {
        int n = __shfl_up_sync(0xffffffffu, inc, d);
        if (lane >= d) inc += n;
    }
    if (lane == 31) wsum[wid] = inc;
    __syncthreads();
    if (wid == 0) {
        int s = wsum[lane];
        #pragma unroll
        for (int d = 1; d < 32; d <<= 1) {
            int n = __shfl_up_sync(0xffffffffu, s, d);
            if (lane >= d) s += n;
        }
        wsum[lane] = s;
    }
    __syncthreads();
    const int ex = inc - v + ((wid > 0) ? wsum[wid - 1] : 0);
    const int total = wsum[31];

    if (t == 0) {
        g_tile_agg[b] = total;
        __threadfence();
        atomicExch(&g_tile_flag[b], 1);
    }

    if (b == 0) {
        if (t < SCAN_BLOCKS) {
            while (atomicAdd(&g_tile_flag[t], 0) == 0) {}
        }
        __syncthreads();
        if (t == 0) {
            int run = 0;
            #pragma unroll 1
            for (int j = 0; j < SCAN_BLOCKS; j++) {
                g_tile_pre[j] = run;
                run += g_tile_agg[j];
            }
            __threadfence();
        }
        __syncthreads();
        if (t < SCAN_BLOCKS) atomicExch(&g_tile_flag[t], 2);
    }

    if (t == 0) {
        while (atomicAdd(&g_tile_flag[b], 0) != 2) {}
        __threadfence();
        sh_pre = g_tile_pre[b];
        atomicExch(&g_tile_flag[b], 0);            // reset own flag for next replay
    }
    __syncthreads();

    int off = sh_pre + ex;
    if (i < N_NODES) { g_off[i] = off; g_cur[i] = off; }
    if (b == 0 && t == 0) g_off[N_NODES] = N_EDGES;
}

// ---------------- projection GEMM: fp16 m16n8k16 via ldmatrix, 128x128 block ----------------
// warp (wm, wn): rows wm*32..+32, cols wn*64..+64 (= exactly one head)
__global__ void __launch_bounds__(256, 2) k_gemm(const float* __restrict__ x,
                                                 const float* __restrict__ att_src,
                                                 const float* __restrict__ att_dst) {
    constexpr int BM = 128, BK = 32;       // K halves per chunk
    constexpr int NCK = IN_CH / BK;        // 8
    constexpr int ASTRW = 20;              // words per smem row (40 halves; conflict-free)
    __shared__ __half As[2][BM * ASTRW * 2];
    __shared__ __half Bs[2][128 * ASTRW * 2];

    const int tid  = threadIdx.x;
    const int lane = tid & 31;
    const int wid  = tid >> 5;
    const int wm   = wid & 3;
    const int wn   = wid >> 2;
    const int m0   = blockIdx.x * BM;
    const int n0   = blockIdx.y * 128;

    float c[2][8][4];
    #pragma unroll
    for (int mt = 0; mt < 2; mt++)
        #pragma unroll
        for (int nt = 0; nt < 8; nt++)
            #pragma unroll
            for (int i = 0; i < 4; i++) c[mt][nt][i] = 0.f;

    // loader: 512 8-half units per tile; thread handles units tid and tid+256
    auto load_chunk = [&](int ck, int buf) {
        #pragma unroll
        for (int t = 0; t < 2; t++) {
            int u = tid + t * 256;       // 0..511
            int r = u >> 2;              // 0..127
            int o = (u & 3) * 8;         // half offset 0,8,16,24
            float4 va = make_float4(0.f, 0.f, 0.f, 0.f), vb = va;
            if (m0 + r < N_NODES) {
                const float* p = x + (size_t)(m0 + r) * IN_CH + ck * BK + o;
                va = *reinterpret_cast<const float4*>(p);
                vb = *reinterpret_cast<const float4*>(p + 4);
            }
            uint4 ha;
            __half2* hp = reinterpret_cast<__half2*>(&ha);
            hp[0] = __float22half2_rn(make_float2(va.x, va.y));
            hp[1] = __float22half2_rn(make_float2(va.z, va.w));
            hp[2] = __float22half2_rn(make_float2(vb.x, vb.y));
            hp[3] = __float22half2_rn(make_float2(vb.z, vb.w));
            *reinterpret_cast<uint4*>(&As[buf][r * (ASTRW * 2) + o]) = ha;
            uint4 hb = *reinterpret_cast<const uint4*>(
                g_wcatT + (size_t)(n0 + r) * IN_CH + ck * BK + o);
            *reinterpret_cast<uint4*>(&Bs[buf][r * (ASTRW * 2) + o]) = hb;
        }
    };

    load_chunk(0, 0);
    __syncthreads();

    const int g  = lane >> 2;   // group id 0..7
    const int tg = lane & 3;    // thread in group 0..3

    // per-lane ldmatrix word offset within a 16x16 (2x2 tiles) block:
    // tile = lane>>3: row += (tile&1)*8, kword += (tile>>1)*4; row-in-tile = lane&7
    const uint32_t loffb = (((lane & 7) + ((lane >> 3) & 1) * 8) * ASTRW + (lane >> 4) * 4) * 4;

    for (int ck = 0; ck < NCK; ck++) {
        const int buf = ck & 1;
        const uint32_t aBase = (uint32_t)__cvta_generic_to_shared(&As[buf][0]) + loffb;
        const uint32_t bBase = (uint32_t)__cvta_generic_to_shared(&Bs[buf][0]) + loffb;
        #pragma unroll
        for (int ks = 0; ks < 2; ks++) {
            const uint32_t kOff = ks * 8 * 4;     // 8 words in bytes
            uint32_t a[2][4];
            #pragma unroll
            for (int mt = 0; mt < 2; mt++) {
                uint32_t addr = aBase + (uint32_t)((wm * 32 + mt * 16) * ASTRW * 4) + kOff;
                ldmx4(a[mt][0], a[mt][1], a[mt][2], a[mt][3], addr);
            }
            #pragma unroll
            for (int q = 0; q < 4; q++) {
                uint32_t addr = bBase + (uint32_t)((wn * 64 + q * 16) * ASTRW * 4) + kOff;
                uint32_t w0, w1, w2, w3;
                ldmx4(w0, w1, w2, w3, addr);
                mma_f16(c[0][2 * q],     a[0], w0, w2);
                mma_f16(c[1][2 * q],     a[1], w0, w2);
                mma_f16(c[0][2 * q + 1], a[0], w1, w3);
                mma_f16(c[1][2 * q + 1], a[1], w1, w3);
            }
        }
        if (ck + 1 < NCK) load_chunk(ck + 1, buf ^ 1);
        __syncthreads();
    }

    // epilogue: fp16 store + fused alpha dot products (exact fp32 accumulators)
    const int h = (n0 + wn * 64) >> 6;          // this warp's head
    #pragma unroll
    for (int mt = 0; mt < 2; mt++) {
        int r1 = wm * 32 + mt * 16 + g;
        int r2 = r1 + 8;
        int m1 = m0 + r1, m2 = m0 + r2;
        float s1 = 0.f, d1 = 0.f, s2 = 0.f, d2 = 0.f;
        #pragma unroll
        for (int nt = 0; nt < 8; nt++) {
            int n = n0 + wn * 64 + nt * 8 + tg * 2;
            float a0 = att_src[n], a1 = att_src[n + 1];
            float b0 = att_dst[n], b1 = att_dst[n + 1];
            s1 += c[mt][nt][0] * a0 + c[mt][nt][1] * a1;
            d1 += c[mt][nt][0] * b0 + c[mt][nt][1] * b1;
            s2 += c[mt][nt][2] * a0 + c[mt][nt][3] * a1;
            d2 += c[mt][nt][2] * b0 + c[mt][nt][3] * b1;
            if (m1 < N_NODES)
                *reinterpret_cast<__half2*>(g_xhh + (size_t)m1 * OUTF + n)
                    = __float22half2_rn(make_float2(c[mt][nt][0], c[mt][nt][1]));
            if (m2 < N_NODES)
                *reinterpret_cast<__half2*>(g_xhh + (size_t)m2 * OUTF + n)
                    = __float22half2_rn(make_float2(c[mt][nt][2], c[mt][nt][3]));
        }
        s1 += __shfl_xor_sync(0xffffffffu, s1, 1); s1 += __shfl_xor_sync(0xffffffffu, s1, 2);
        d1 += __shfl_xor_sync(0xffffffffu, d1, 1); d1 += __shfl_xor_sync(0xffffffffu, d1, 2);
        s2 += __shfl_xor_sync(0xffffffffu, s2, 1); s2 += __shfl_xor_sync(0xffffffffu, s2, 2);
        d2 += __shfl_xor_sync(0xffffffffu, d2, 1); d2 += __shfl_xor_sync(0xffffffffu, d2, 2);
        if (tg == 0) {
            if (m1 < N_NODES) { g_asrc[m1 * 4 + h] = s1; g_adst[m1 * 4 + h] = d1; }
            if (m2 < N_NODES) { g_asrc[m2 * 4 + h] = s2; g_adst[m2 * 4 + h] = d2; }
        }
    }
}

// ---------------- fused edge pass: logits -> exp, reorder into CSR slots ----------------
__global__ void k_edge_fused(const int* __restrict__ ei) {
    int e = blockIdx.x * blockDim.x + threadIdx.x;
    if (e >= N_EDGES) return;
    int row = clamp_idx(ei[e]);
    int col = clamp_idx(ei[N_EDGES + e]);
    float4 s = *reinterpret_cast<const float4*>(g_asrc + row * 4);
    float4 d = *reinterpret_cast<const float4*>(g_adst + col * 4);
    float a0 = s.x + d.x, a1 = s.y + d.y, a2 = s.z + d.z, a3 = s.w + d.w;
    a0 = a0 > 0.f ? a0 : 0.2f * a0;
    a1 = a1 > 0.f ? a1 : 0.2f * a1;
    a2 = a2 > 0.f ? a2 : 0.2f * a2;
    a3 = a3 > 0.f ? a3 : 0.2f * a3;
    float4 p = make_float4(__expf(a0), __expf(a1), __expf(a2), __expf(a3));
    int pos = atomicAdd(&g_cur[row], 1);
    g_ecol[pos] = col;
    *reinterpret_cast<float4*>(g_eexp + (size_t)pos * 4) = p;
}

// ---------------- CSR gather: warp per node, software-pipelined ----------------
__global__ void k_csr(const float* __restrict__ bias, float* __restrict__ out) {
    int warp = (blockIdx.x * blockDim.x + threadIdx.x) >> 5;
    if (warp >= N_NODES) return;
    int lane = threadIdx.x & 31;
    int n = warp;
    int off = g_off[n];
    int deg = g_off[n + 1] - off;
    const int head = lane >> 3;   // channels lane*8..lane*8+7 all in this head

    float acc[8];
    #pragma unroll
    for (int k = 0; k < 8; k++) acc[k] = 0.f;
    float den = 0.f;

    const uint4*  xb = reinterpret_cast<const uint4*>(g_xhh);   // 8 fp16 per uint4, 32 per row
    const float4* pe = reinterpret_cast<const float4*>(g_eexp);

    int    c_cur = 0, c_nxt = 0;
    float4 p_cur = make_float4(0.f, 0.f, 0.f, 0.f), p_nxt = p_cur;
    uint4  v_cur = make_uint4(0u, 0u, 0u, 0u);
    if (deg > 0) { c_cur = g_ecol[off];     p_cur = pe[off];     v_cur = xb[(size_t)c_cur * 32 + lane]; }
    if (deg > 1) { c_nxt = g_ecol[off + 1]; p_nxt = pe[off + 1]; }

    for (int j = 0; j < deg; j++) {
        uint4  v = v_cur;
        float4 p = p_cur;
        int    c2 = c_nxt;
        float4 p2 = p_nxt;
        if (j + 2 < deg) { c_nxt = g_ecol[off + j + 2]; p_nxt = pe[off + j + 2]; }
        if (j + 1 < deg) { v_cur = xb[(size_t)c2 * 32 + lane]; p_cur = p2; }

        float pa = (head == 0) ? p.x : (head == 1) ? p.y : (head == 2) ? p.z : p.w;
        den += pa;
        float2 f0 = __half22float2(*reinterpret_cast<__half2*>(&v.x));
        float2 f1 = __half22float2(*reinterpret_cast<__half2*>(&v.y));
        float2 f2 = __half22float2(*reinterpret_cast<__half2*>(&v.z));
        float2 f3 = __half22float2(*reinterpret_cast<__half2*>(&v.w));
        acc[0] = fmaf(pa, f0.x, acc[0]); acc[1] = fmaf(pa, f0.y, acc[1]);
        acc[2] = fmaf(pa, f1.x, acc[2]); acc[3] = fmaf(pa, f1.y, acc[3]);
        acc[4] = fmaf(pa, f2.x, acc[4]); acc[5] = fmaf(pa, f2.y, acc[5]);
        acc[6] = fmaf(pa, f3.x, acc[6]); acc[7] = fmaf(pa, f3.y, acc[7]);
    }

    float r = 1.f / fmaxf(den, 1e-16f);
    const float4* b4 = reinterpret_cast<const float4*>(bias) + lane * 2;
    float4 b0 = b4[0], b1 = b4[1];
    float4 o0, o1;
    o0.x = fmaf(acc[0], r, b0.x); o0.y = fmaf(acc[1], r, b0.y);
    o0.z = fmaf(acc[2], r, b0.z); o0.w = fmaf(acc[3], r, b0.w);
    o1.x = fmaf(acc[4], r, b1.x); o1.y = fmaf(acc[5], r, b1.y);
    o1.z = fmaf(acc[6], r, b1.z); o1.w = fmaf(acc[7], r, b1.w);
    float4* dst = reinterpret_cast<float4*>(out) + (size_t)n * 64 + lane * 2;
    dst[0] = o0;
    dst[1] = o1;
}

// ---------------- launch ----------------
extern "C" void kernel_launch(void* const* d_in, const int* in_sizes, int n_in,
                              void* d_out, int out_size) {
    const float* x       = (const float*)d_in[0];
    const int*   ei      = (const int*)d_in[1];       // int32 (JAX x64 disabled)
    const float* w       = (const float*)d_in[2];
    const float* att_src = (const float*)d_in[3];
    const float* att_dst = (const float*)d_in[4];
    const float* bias    = (const float*)d_in[5];
    float*       out     = (float*)d_out;

    k_hist<<<(N_EDGES + 255) / 256, 256>>>(ei, w);
    k_scanL<<<SCAN_BLOCKS, 1024>>>();

    dim3 gg((N_NODES + 127) / 128, OUTF / 128);
    k_gemm<<<gg, 256>>>(x, att_src, att_dst);

    k_edge_fused<<<(N_EDGES + 255) / 256, 256>>>(ei);
    k_csr<<<(N_NODES * 32 + 255) / 256, 256>>>(bias, out);
}

// round 16
// speedup vs baseline: 1.1105x; 1.1105x over previous
#include <cuda_runtime.h>
#include <cuda_fp16.h>
#include <cstdint>

#define N_NODES 50000
#define N_PAD   50048              // 128*391, padded for cp.async tiles
#define N_EDGES 800000
#define IN_CH   256
#define OUT_CH  64
#define HEADS   4
#define OUTF    (HEADS * OUT_CH)   // 256

#define SCAN_BLOCKS 49             // ceil(50000/1024)

// ---------------- device scratch (no allocs allowed) ----------------
__device__ __align__(16) __half g_xf16[(size_t)N_PAD * IN_CH];  // x in fp16 (padded, zero-filled)
__device__ __align__(16) __half g_xhh[(size_t)N_NODES * OUTF];  // projected features, fp16
__device__ __align__(16) __half g_wcatT[OUTF * IN_CH];          // weight^T fp16: [n=256][k=256]
__device__ __align__(16) float g_asrc[N_NODES * HEADS];         // [N, 4]
__device__ __align__(16) float g_adst[N_NODES * HEADS];         // [N, 4]
__device__ int g_cnt[N_NODES];                                  // per-row edge count (self-zeroing)
__device__ int g_off[N_NODES + 1];                              // CSR offsets
__device__ int g_cur[N_NODES];                                  // reorder cursors
__device__ int g_tile_agg[64];                                  // scan tile aggregates
__device__ int g_tile_pre[64];                                  // scan tile prefixes
__device__ int g_tile_flag[64];                                 // 0=empty,1=agg,2=prefix (self-zeroing)
__device__ int g_ecol[N_EDGES];                                 // CSR col per slot
__device__ __align__(16) uint2 g_eexp[N_EDGES];                 // CSR 4x fp16 exp(logit) per slot

__device__ __forceinline__ int clamp_idx(int v) {
    return min(max(v, 0), N_NODES - 1);
}

__device__ __forceinline__ void mma_f16(float* c, const uint32_t* a, uint32_t b0, uint32_t b1) {
    asm("mma.sync.aligned.m16n8k16.row.col.f32.f16.f16.f32 "
        "{%0,%1,%2,%3}, {%4,%5,%6,%7}, {%8,%9}, {%0,%1,%2,%3};"
        : "+f"(c[0]), "+f"(c[1]), "+f"(c[2]), "+f"(c[3])
        : "r"(a[0]), "r"(a[1]), "r"(a[2]), "r"(a[3]), "r"(b0), "r"(b1));
}

__device__ __forceinline__ void ldmx4(uint32_t& r0, uint32_t& r1, uint32_t& r2, uint32_t& r3,
                                      uint32_t addr) {
    asm volatile("ldmatrix.sync.aligned.m8n8.x4.shared.b16 {%0,%1,%2,%3}, [%4];"
                 : "=r"(r0), "=r"(r1), "=r"(r2), "=r"(r3) : "r"(addr));
}

__device__ __forceinline__ void cp_async16(uint32_t smem_addr, const void* gptr) {
    asm volatile("cp.async.cg.shared.global [%0], [%1], 16;"
                 :: "r"(smem_addr), "l"(gptr) : "memory");
}
__device__ __forceinline__ void cp_commit() {
    asm volatile("cp.async.commit_group;" ::: "memory");
}
__device__ __forceinline__ void cp_wait0() {
    asm volatile("cp.async.wait_group 0;" ::: "memory");
}

// ---------------- hist + weight transpose + x->fp16 (merged) ----------------
__global__ void k_hist(const int* __restrict__ ei, const float* __restrict__ w,
                       const float* __restrict__ x) {
    int i = blockIdx.x * blockDim.x + threadIdx.x;
    // x conversion: unit = 8 halves; N_PAD*256/8 = 1601536 units
    if (i < N_PAD * (IN_CH / 8)) {
        int r = i >> 5;               // row
        int o = (i & 31) * 8;         // half offset in row
        uint4 h;
        if (r < N_NODES) {
            const float* p = x + (size_t)r * IN_CH + o;
            float4 va = *reinterpret_cast<const float4*>(p);
            float4 vb = *reinterpret_cast<const float4*>(p + 4);
            __half2* hp = reinterpret_cast<__half2*>(&h);
            hp[0] = __float22half2_rn(make_float2(va.x, va.y));
            hp[1] = __float22half2_rn(make_float2(va.z, va.w));
            hp[2] = __float22half2_rn(make_float2(vb.x, vb.y));
            hp[3] = __float22half2_rn(make_float2(vb.z, vb.w));
        } else {
            h = make_uint4(0u, 0u, 0u, 0u);
        }
        *reinterpret_cast<uint4*>(g_xf16 + (size_t)r * IN_CH + o) = h;
    }
    if (i < HEADS * IN_CH * OUT_CH) {
        int h = i >> 14;
        int f = (i >> 6) & 255;
        int c = i & 63;
        g_wcatT[(size_t)(h * OUT_CH + c) * IN_CH + f] = __float2half(w[i]);
    }
    if (i < N_EDGES) atomicAdd(&g_cnt[clamp_idx(ei[i])], 1);
}

// ---------------- single-kernel scan: 49 co-resident blocks; self-cleaning ----------------
__global__ void k_scanL() {
    __shared__ int wsum[32];
    __shared__ int sh_pre;
    const int b = blockIdx.x;
    const int t = threadIdx.x;
    const int i = b * 1024 + t;
    const int lane = t & 31, wid = t >> 5;

    int v = (i < N_NODES) ? g_cnt[i] : 0;
    if (i < N_NODES) g_cnt[i] = 0;                 // reset for next graph replay
    int inc = v;
    #pragma unroll
    for (int d = 1; d < 32; d <<= 1) {
        int n = __shfl_up_sync(0xffffffffu, inc, d);
        if (lane >= d) inc += n;
    }
    if (lane == 31) wsum[wid] = inc;
    __syncthreads();
    if (wid == 0) {
        int s = wsum[lane];
        #pragma unroll
        for (int d = 1; d < 32; d <<= 1) {
            int n = __shfl_up_sync(0xffffffffu, s, d);
            if (lane >= d) s += n;
        }
        wsum[lane] = s;
    }
    __syncthreads();
    const int ex = inc - v + ((wid > 0) ? wsum[wid - 1] : 0);
    const int total = wsum[31];

    if (t == 0) {
        g_tile_agg[b] = total;
        __threadfence();
        atomicExch(&g_tile_flag[b], 1);
    }

    if (b == 0) {
        if (t < SCAN_BLOCKS) {
            while (atomicAdd(&g_tile_flag[t], 0) == 0) {}
        }
        __syncthreads();
        if (t == 0) {
            int run = 0;
            #pragma unroll 1
            for (int j = 0; j < SCAN_BLOCKS; j++) {
                g_tile_pre[j] = run;
                run += g_tile_agg[j];
            }
            __threadfence();
        }
        __syncthreads();
        if (t < SCAN_BLOCKS) atomicExch(&g_tile_flag[t], 2);
    }

    if (t == 0) {
        while (atomicAdd(&g_tile_flag[b], 0) != 2) {}
        __threadfence();
        sh_pre = g_tile_pre[b];
        atomicExch(&g_tile_flag[b], 0);            // reset own flag for next replay
    }
    __syncthreads();

    int off = sh_pre + ex;
    if (i < N_NODES) { g_off[i] = off; g_cur[i] = off; }
    if (b == 0 && t == 0) g_off[N_NODES] = N_EDGES;
}

// ---------------- projection GEMM: fp16 m16n8k16, cp.async double-buffered ----------------
// warp (wm, wn): rows wm*32..+32, cols wn*64..+64 (= exactly one head)
__global__ void __launch_bounds__(256, 2) k_gemm(const float* __restrict__ att_src,
                                                 const float* __restrict__ att_dst) {
    constexpr int BM = 128, BK = 32;       // K halves per chunk
    constexpr int NCK = IN_CH / BK;        // 8
    constexpr int ASTRW = 20;              // words per smem row (40 halves; conflict-free)
    __shared__ __half As[2][BM * ASTRW * 2];
    __shared__ __half Bs[2][128 * ASTRW * 2];

    const int tid  = threadIdx.x;
    const int lane = tid & 31;
    const int wid  = tid >> 5;
    const int wm   = wid & 3;
    const int wn   = wid >> 2;
    const int m0   = blockIdx.x * BM;
    const int n0   = blockIdx.y * 128;

    float c[2][8][4];
    #pragma unroll
    for (int mt = 0; mt < 2; mt++)
        #pragma unroll
        for (int nt = 0; nt < 8; nt++)
            #pragma unroll
            for (int i = 0; i < 4; i++) c[mt][nt][i] = 0.f;

    // cp.async loader: 512 16B units per matrix tile; thread handles units tid, tid+256
    const int ur = tid >> 2;               // 0..63 then +64
    const int uo = (tid & 3) * 8;          // half offset 0,8,16,24
    auto issue_loads = [&](int ck, int buf) {
        #pragma unroll
        for (int t = 0; t < 2; t++) {
            int r = ur + t * 64;           // 0..127
            uint32_t dA = (uint32_t)__cvta_generic_to_shared(
                &As[buf][r * (ASTRW * 2) + uo]);
            cp_async16(dA, g_xf16 + (size_t)(m0 + r) * IN_CH + ck * BK + uo);
            uint32_t dB = (uint32_t)__cvta_generic_to_shared(
                &Bs[buf][r * (ASTRW * 2) + uo]);
            cp_async16(dB, g_wcatT + (size_t)(n0 + r) * IN_CH + ck * BK + uo);
        }
        cp_commit();
    };

    issue_loads(0, 0);

    const int g  = lane >> 2;   // group id 0..7
    const int tg = lane & 3;    // thread in group 0..3
    const uint32_t loffb = (((lane & 7) + ((lane >> 3) & 1) * 8) * ASTRW + (lane >> 4) * 4) * 4;

    for (int ck = 0; ck < NCK; ck++) {
        const int buf = ck & 1;
        cp_wait0();
        __syncthreads();                   // chunk ck in smem; prior compute done everywhere
        if (ck + 1 < NCK) issue_loads(ck + 1, buf ^ 1);   // overlaps with compute below

        const uint32_t aBase = (uint32_t)__cvta_generic_to_shared(&As[buf][0]) + loffb;
        const uint32_t bBase = (uint32_t)__cvta_generic_to_shared(&Bs[buf][0]) + loffb;
        #pragma unroll
        for (int ks = 0; ks < 2; ks++) {
            const uint32_t kOff = ks * 8 * 4;
            uint32_t a[2][4];
            #pragma unroll
            for (int mt = 0; mt < 2; mt++) {
                uint32_t addr = aBase + (uint32_t)((wm * 32 + mt * 16) * ASTRW * 4) + kOff;
                ldmx4(a[mt][0], a[mt][1], a[mt][2], a[mt][3], addr);
            }
            #pragma unroll
            for (int q = 0; q < 4; q++) {
                uint32_t addr = bBase + (uint32_t)((wn * 64 + q * 16) * ASTRW * 4) + kOff;
                uint32_t w0, w1, w2, w3;
                ldmx4(w0, w1, w2, w3, addr);
                mma_f16(c[0][2 * q],     a[0], w0, w2);
                mma_f16(c[1][2 * q],     a[1], w0, w2);
                mma_f16(c[0][2 * q + 1], a[0], w1, w3);
                mma_f16(c[1][2 * q + 1], a[1], w1, w3);
            }
        }
    }

    // epilogue: fp16 store + fused alpha dot products (exact fp32 accumulators)
    const int h = (n0 + wn * 64) >> 6;          // this warp's head
    #pragma unroll
    for (int mt = 0; mt < 2; mt++) {
        int r1 = wm * 32 + mt * 16 + g;
        int r2 = r1 + 8;
        int m1 = m0 + r1, m2 = m0 + r2;
        float s1 = 0.f, d1 = 0.f, s2 = 0.f, d2 = 0.f;
        #pragma unroll
        for (int nt = 0; nt < 8; nt++) {
            int n = n0 + wn * 64 + nt * 8 + tg * 2;
            float a0 = att_src[n], a1 = att_src[n + 1];
            float b0 = att_dst[n], b1 = att_dst[n + 1];
            s1 += c[mt][nt][0] * a0 + c[mt][nt][1] * a1;
            d1 += c[mt][nt][0] * b0 + c[mt][nt][1] * b1;
            s2 += c[mt][nt][2] * a0 + c[mt][nt][3] * a1;
            d2 += c[mt][nt][2] * b0 + c[mt][nt][3] * b1;
            if (m1 < N_NODES)
                *reinterpret_cast<__half2*>(g_xhh + (size_t)m1 * OUTF + n)
                    = __float22half2_rn(make_float2(c[mt][nt][0], c[mt][nt][1]));
            if (m2 < N_NODES)
                *reinterpret_cast<__half2*>(g_xhh + (size_t)m2 * OUTF + n)
                    = __float22half2_rn(make_float2(c[mt][nt][2], c[mt][nt][3]));
        }
        s1 += __shfl_xor_sync(0xffffffffu, s1, 1); s1 += __shfl_xor_sync(0xffffffffu, s1, 2);
        d1 += __shfl_xor_sync(0xffffffffu, d1, 1); d1 += __shfl_xor_sync(0xffffffffu, d1, 2);
        s2 += __shfl_xor_sync(0xffffffffu, s2, 1); s2 += __shfl_xor_sync(0xffffffffu, s2, 2);
        d2 += __shfl_xor_sync(0xffffffffu, d2, 1); d2 += __shfl_xor_sync(0xffffffffu, d2, 2);
        if (tg == 0) {
            if (m1 < N_NODES) { g_asrc[m1 * 4 + h] = s1; g_adst[m1 * 4 + h] = d1; }
            if (m2 < N_NODES) { g_asrc[m2 * 4 + h] = s2; g_adst[m2 * 4 + h] = d2; }
        }
    }
}

// ---------------- fused edge pass: logits -> exp (fp16 packed), reorder into CSR ----------------
__global__ void k_edge_fused(const int* __restrict__ ei) {
    int e = blockIdx.x * blockDim.x + threadIdx.x;
    if (e >= N_EDGES) return;
    int row = clamp_idx(ei[e]);
    int col = clamp_idx(ei[N_EDGES + e]);
    float4 s = *reinterpret_cast<const float4*>(g_asrc + row * 4);
    float4 d = *reinterpret_cast<const float4*>(g_adst + col * 4);
    float a0 = s.x + d.x, a1 = s.y + d.y, a2 = s.z + d.z, a3 = s.w + d.w;
    a0 = a0 > 0.f ? a0 : 0.2f * a0;
    a1 = a1 > 0.f ? a1 : 0.2f * a1;
    a2 = a2 > 0.f ? a2 : 0.2f * a2;
    a3 = a3 > 0.f ? a3 : 0.2f * a3;
    uint2 pk;
    *reinterpret_cast<__half2*>(&pk.x) = __float22half2_rn(make_float2(__expf(a0), __expf(a1)));
    *reinterpret_cast<__half2*>(&pk.y) = __float22half2_rn(make_float2(__expf(a2), __expf(a3)));
    int pos = atomicAdd(&g_cur[row], 1);
    g_ecol[pos] = col;
    g_eexp[pos] = pk;
}

// ---------------- CSR gather: warp per node, software-pipelined ----------------
__global__ void k_csr(const float* __restrict__ bias, float* __restrict__ out) {
    int warp = (blockIdx.x * blockDim.x + threadIdx.x) >> 5;
    if (warp >= N_NODES) return;
    int lane = threadIdx.x & 31;
    int n = warp;
    int off = g_off[n];
    int deg = g_off[n + 1] - off;
    const int head = lane >> 3;   // channels lane*8..lane*8+7 all in this head

    float acc[8];
    #pragma unroll
    for (int k = 0; k < 8; k++) acc[k] = 0.f;
    float den = 0.f;

    const uint4* xb = reinterpret_cast<const uint4*>(g_xhh);   // 8 fp16 per uint4, 32 per row

    int   c_cur = 0, c_nxt = 0;
    uint2 p_cur = make_uint2(0u, 0u), p_nxt = p_cur;
    uint4 v_cur = make_uint4(0u, 0u, 0u, 0u);
    if (deg > 0) { c_cur = g_ecol[off];     p_cur = g_eexp[off];     v_cur = xb[(size_t)c_cur * 32 + lane]; }
    if (deg > 1) { c_nxt = g_ecol[off + 1]; p_nxt = g_eexp[off + 1]; }

    for (int j = 0; j < deg; j++) {
        uint4 v = v_cur;
        uint2 p = p_cur;
        int   c2 = c_nxt;
        uint2 p2 = p_nxt;
        if (j + 2 < deg) { c_nxt = g_ecol[off + j + 2]; p_nxt = g_eexp[off + j + 2]; }
        if (j + 1 < deg) { v_cur = xb[(size_t)c2 * 32 + lane]; p_cur = p2; }

        float2 q0 = __half22float2(*reinterpret_cast<__half2*>(&p.x));
        float2 q1 = __half22float2(*reinterpret_cast<__half2*>(&p.y));
        float pa = (head == 0) ? q0.x : (head == 1) ? q0.y : (head == 2) ? q1.x : q1.y;
        den += pa;
        float2 f0 = __half22float2(*reinterpret_cast<__half2*>(&v.x));
        float2 f1 = __half22float2(*reinterpret_cast<__half2*>(&v.y));
        float2 f2 = __half22float2(*reinterpret_cast<__half2*>(&v.z));
        float2 f3 = __half22float2(*reinterpret_cast<__half2*>(&v.w));
        acc[0] = fmaf(pa, f0.x, acc[0]); acc[1] = fmaf(pa, f0.y, acc[1]);
        acc[2] = fmaf(pa, f1.x, acc[2]); acc[3] = fmaf(pa, f1.y, acc[3]);
        acc[4] = fmaf(pa, f2.x, acc[4]); acc[5] = fmaf(pa, f2.y, acc[5]);
        acc[6] = fmaf(pa, f3.x, acc[6]); acc[7] = fmaf(pa, f3.y, acc[7]);
    }

    float r = 1.f / fmaxf(den, 1e-16f);
    const float4* b4 = reinterpret_cast<const float4*>(bias) + lane * 2;
    float4 b0 = b4[0], b1 = b4[1];
    float4 o0, o1;
    o0.x = fmaf(acc[0], r, b0.x); o0.y = fmaf(acc[1], r, b0.y);
    o0.z = fmaf(acc[2], r, b0.z); o0.w = fmaf(acc[3], r, b0.w);
    o1.x = fmaf(acc[4], r, b1.x); o1.y = fmaf(acc[5], r, b1.y);
    o1.z = fmaf(acc[6], r, b1.z); o1.w = fmaf(acc[7], r, b1.w);
    float4* dst = reinterpret_cast<float4*>(out) + (size_t)n * 64 + lane * 2;
    dst[0] = o0;
    dst[1] = o1;
}

// ---------------- launch ----------------
extern "C" void kernel_launch(void* const* d_in, const int* in_sizes, int n_in,
                              void* d_out, int out_size) {
    const float* x       = (const float*)d_in[0];
    const int*   ei      = (const int*)d_in[1];       // int32 (JAX x64 disabled)
    const float* w       = (const float*)d_in[2];
    const float* att_src = (const float*)d_in[3];
    const float* att_dst = (const float*)d_in[4];
    const float* bias    = (const float*)d_in[5];
    float*       out     = (float*)d_out;

    const int HIST_UNITS = N_PAD * (IN_CH / 8);       // 1,601,536 (covers all merged jobs)
    k_hist<<<(HIST_UNITS + 255) / 256, 256>>>(ei, w, x);
    k_scanL<<<SCAN_BLOCKS, 1024>>>();

    dim3 gg((N_NODES + 127) / 128, OUTF / 128);
    k_gemm<<<gg, 256>>>(att_src, att_dst);

    k_edge_fused<<<(N_EDGES + 255) / 256, 256>>>(ei);
    k_csr<<<(N_NODES * 32 + 255) / 256, 256>>>(bias, out);
}